// round 2
// baseline (speedup 1.0000x reference)
#include <cuda_runtime.h>

#define BB    8
#define CIN   67
#define CINP  68          // padded (row 67 zeroed)
#define C2    128
#define CO    64
#define NN    16384
#define EPSV  1e-5f
#define TN    128         // n-tile
#define SPLITS 32         // pass1 splits per batch
#define NPART (BB * SPLITS)      // 256 pass1 blocks
#define TILES_PER_SPLIT 4        // 512 n per split / TN

// ---------------- device scratch (no allocations allowed) ----------------
__device__ __align__(16) float g_Wq[CINP][C2];   // folded, transposed: [k][o]
__device__ __align__(16) float g_Wk[CINP][C2];
__device__ __align__(16) float g_Wv[CINP][C2];
__device__ __align__(16) float g_bq[C2];
__device__ __align__(16) float g_bk[C2];
__device__ __align__(16) float g_bv[C2];
__device__ __align__(16) float g_Wf[CO][C2];     // folded, natural: [o][d]
__device__ __align__(16) float g_bf[CO];
__device__ __align__(16) float g_MT[BB][C2][CO]; // MT[b][c][o] = M[b][o][c]
__device__ __align__(16) float g_kvpart[NPART][C2 * C2];

// ---------------- prep: fold BN into weights/biases ----------------
__global__ void prep_kernel(const float* __restrict__ Wq, const float* __restrict__ Wk,
                            const float* __restrict__ Wv, const float* __restrict__ Wf,
                            const float* __restrict__ bnq, const float* __restrict__ bnk,
                            const float* __restrict__ bnv, const float* __restrict__ bnf) {
    __shared__ float sq[C2], sk[C2], sv[C2], sf[CO];
    int tid = threadIdx.x;
    if (tid < C2) {
        float s;
        s = bnq[tid] * rsqrtf(bnq[3 * C2 + tid] + EPSV);
        sq[tid] = s; g_bq[tid] = bnq[C2 + tid] - bnq[2 * C2 + tid] * s;
        s = bnk[tid] * rsqrtf(bnk[3 * C2 + tid] + EPSV);
        sk[tid] = s; g_bk[tid] = bnk[C2 + tid] - bnk[2 * C2 + tid] * s;
        s = bnv[tid] * rsqrtf(bnv[3 * C2 + tid] + EPSV);
        sv[tid] = s; g_bv[tid] = bnv[C2 + tid] - bnv[2 * C2 + tid] * s;
    }
    if (tid < CO) {
        float s = bnf[tid] * rsqrtf(bnf[3 * CO + tid] + EPSV);
        sf[tid] = s; g_bf[tid] = bnf[CO + tid] - bnf[2 * CO + tid] * s;
    }
    __syncthreads();
    for (int idx = tid; idx < CINP * C2; idx += blockDim.x) {
        int k = idx >> 7, o = idx & 127;
        float wq = 0.f, wk = 0.f, wv = 0.f;
        if (k < CIN) {
            wq = Wq[o * CIN + k] * sq[o];
            wk = Wk[o * CIN + k] * sk[o];
            wv = Wv[o * CIN + k] * sv[o];
        }
        g_Wq[k][o] = wq; g_Wk[k][o] = wk; g_Wv[k][o] = wv;
    }
    for (int idx = tid; idx < CO * C2; idx += blockDim.x) {
        int o = idx >> 7;
        g_Wf[0][idx] = Wf[idx] * sf[o];
    }
}

// ---------------- shared GEMM micro-kernel: C[128][TN] = W(128x68) @ xs(68xTN) ----------------
// W is [CINP][C2] (k-major, transposed). Output ReLU(acc + bias).
// TRANS=true  -> store outT[n][o] (stride C2)   (for ksT / vsT)
// TRANS=false -> store out[o][n]  (stride TN)   (for qs)
template <bool TRANS>
__device__ __forceinline__ void gemm_wx(const float* __restrict__ W,
                                        const float* __restrict__ xs,
                                        const float* __restrict__ gbias,
                                        float* __restrict__ osm,
                                        int r0, int c0) {
    float acc[8][8];
#pragma unroll
    for (int i = 0; i < 8; ++i)
#pragma unroll
        for (int j = 0; j < 8; ++j) acc[i][j] = 0.f;

#pragma unroll 4
    for (int k = 0; k < CINP; ++k) {
        const float4 a0 = *reinterpret_cast<const float4*>(W + k * C2 + r0);
        const float4 a1 = *reinterpret_cast<const float4*>(W + k * C2 + r0 + 4);
        const float4 b0 = *reinterpret_cast<const float4*>(xs + k * TN + c0);
        const float4 b1 = *reinterpret_cast<const float4*>(xs + k * TN + c0 + 4);
        const float av[8] = {a0.x, a0.y, a0.z, a0.w, a1.x, a1.y, a1.z, a1.w};
        const float bv[8] = {b0.x, b0.y, b0.z, b0.w, b1.x, b1.y, b1.z, b1.w};
#pragma unroll
        for (int i = 0; i < 8; ++i)
#pragma unroll
            for (int j = 0; j < 8; ++j) acc[i][j] = fmaf(av[i], bv[j], acc[i][j]);
    }
    float bias[8];
#pragma unroll
    for (int i = 0; i < 8; ++i) bias[i] = gbias[r0 + i];

    if (TRANS) {
#pragma unroll
        for (int j = 0; j < 8; ++j) {
            float4 lo, hi;
            lo.x = fmaxf(acc[0][j] + bias[0], 0.f);
            lo.y = fmaxf(acc[1][j] + bias[1], 0.f);
            lo.z = fmaxf(acc[2][j] + bias[2], 0.f);
            lo.w = fmaxf(acc[3][j] + bias[3], 0.f);
            hi.x = fmaxf(acc[4][j] + bias[4], 0.f);
            hi.y = fmaxf(acc[5][j] + bias[5], 0.f);
            hi.z = fmaxf(acc[6][j] + bias[6], 0.f);
            hi.w = fmaxf(acc[7][j] + bias[7], 0.f);
            *reinterpret_cast<float4*>(osm + (c0 + j) * C2 + r0)     = lo;
            *reinterpret_cast<float4*>(osm + (c0 + j) * C2 + r0 + 4) = hi;
        }
    } else {
#pragma unroll
        for (int i = 0; i < 8; ++i) {
            float4 lo, hi;
            lo.x = fmaxf(acc[i][0] + bias[i], 0.f);
            lo.y = fmaxf(acc[i][1] + bias[i], 0.f);
            lo.z = fmaxf(acc[i][2] + bias[i], 0.f);
            lo.w = fmaxf(acc[i][3] + bias[i], 0.f);
            hi.x = fmaxf(acc[i][4] + bias[i], 0.f);
            hi.y = fmaxf(acc[i][5] + bias[i], 0.f);
            hi.z = fmaxf(acc[i][6] + bias[i], 0.f);
            hi.w = fmaxf(acc[i][7] + bias[i], 0.f);
            *reinterpret_cast<float4*>(osm + (r0 + i) * TN + c0)     = lo;
            *reinterpret_cast<float4*>(osm + (r0 + i) * TN + c0 + 4) = hi;
        }
    }
}

// ---------------- pass 1: k,v GEMMs + kv outer-product accumulation ----------------
// smem: xs[CINP][TN] | ksT[TN][C2] | vsT[TN][C2]
__global__ void __launch_bounds__(256, 1)
pass1_kernel(const float* __restrict__ x) {
    extern __shared__ float smem[];
    float* xs  = smem;                      // CINP*TN
    float* ksT = smem + CINP * TN;          // TN*C2
    float* vsT = ksT + TN * C2;             // TN*C2

    const int tid = threadIdx.x;
    const int tx = tid & 15, ty = tid >> 4;
    const int r0 = ty * 8, c0 = tx * 8;
    const int b = blockIdx.x >> 5, split = blockIdx.x & 31;
    const float* xb = x + (size_t)b * CIN * NN;

    float kvacc[8][8];
#pragma unroll
    for (int i = 0; i < 8; ++i)
#pragma unroll
        for (int j = 0; j < 8; ++j) kvacc[i][j] = 0.f;

    if (tid < TN) xs[CIN * TN + tid] = 0.f;   // zero padded row 67

    for (int t = 0; t < TILES_PER_SPLIT; ++t) {
        const int n0 = split * (TILES_PER_SPLIT * TN) + t * TN;
        for (int idx = tid; idx < CIN * TN; idx += 256) {
            int k = idx >> 7, n = idx & 127;
            xs[idx] = xb[k * NN + n0 + n];
        }
        __syncthreads();

        gemm_wx<true>(&g_Wk[0][0], xs, g_bk, ksT, r0, c0);
        gemm_wx<true>(&g_Wv[0][0], xs, g_bv, vsT, r0, c0);
        __syncthreads();

        // kv[c][d] += sum_n k[c][n] * v[d][n]
        const float4* k4 = reinterpret_cast<const float4*>(ksT);
        const float4* v4 = reinterpret_cast<const float4*>(vsT);
        const int ra = r0 >> 2, cb = c0 >> 2;
#pragma unroll 4
        for (int n = 0; n < TN; ++n) {
            const float4 a0 = k4[n * 32 + ra];
            const float4 a1 = k4[n * 32 + ra + 1];
            const float4 b0 = v4[n * 32 + cb];
            const float4 b1 = v4[n * 32 + cb + 1];
            const float av[8] = {a0.x, a0.y, a0.z, a0.w, a1.x, a1.y, a1.z, a1.w};
            const float bv[8] = {b0.x, b0.y, b0.z, b0.w, b1.x, b1.y, b1.z, b1.w};
#pragma unroll
            for (int i = 0; i < 8; ++i)
#pragma unroll
                for (int j = 0; j < 8; ++j) kvacc[i][j] = fmaf(av[i], bv[j], kvacc[i][j]);
        }
        __syncthreads();   // ksT/vsT reads done before next tile overwrites
    }

    float* part = g_kvpart[blockIdx.x];
#pragma unroll
    for (int i = 0; i < 8; ++i) {
        float4 lo = {kvacc[i][0], kvacc[i][1], kvacc[i][2], kvacc[i][3]};
        float4 hi = {kvacc[i][4], kvacc[i][5], kvacc[i][6], kvacc[i][7]};
        *reinterpret_cast<float4*>(part + (r0 + i) * C2 + c0)     = lo;
        *reinterpret_cast<float4*>(part + (r0 + i) * C2 + c0 + 4) = hi;
    }
}

// ---------------- reduce kv partials + form MT[b][c][o] = sum_d Wf'[o][d]*kv[c][d] ----------------
__global__ void mkernel(void) {
    extern __shared__ float kvs[];   // C2*C2
    const int b = blockIdx.x, tid = threadIdx.x;
    for (int idx = tid; idx < C2 * C2; idx += 256) {
        float s = 0.f;
#pragma unroll
        for (int p = 0; p < SPLITS; ++p) s += g_kvpart[b * SPLITS + p][idx];
        kvs[idx] = s;
    }
    __syncthreads();

    const int tx = tid & 15, ty = tid >> 4;
    const int o0 = ty * 4, c0 = tx * 8;
    float acc[4][8];
#pragma unroll
    for (int i = 0; i < 4; ++i)
#pragma unroll
        for (int j = 0; j < 8; ++j) acc[i][j] = 0.f;

    for (int d = 0; d < C2; ++d) {
        float a[4], bv[8];
#pragma unroll
        for (int i = 0; i < 4; ++i) a[i] = g_Wf[o0 + i][d];
#pragma unroll
        for (int j = 0; j < 8; ++j) bv[j] = kvs[(c0 + j) * C2 + d];
#pragma unroll
        for (int i = 0; i < 4; ++i)
#pragma unroll
            for (int j = 0; j < 8; ++j) acc[i][j] = fmaf(a[i], bv[j], acc[i][j]);
    }
#pragma unroll
    for (int j = 0; j < 8; ++j) {
        float4 v = {acc[0][j], acc[1][j], acc[2][j], acc[3][j]};
        *reinterpret_cast<float4*>(&g_MT[b][c0 + j][o0]) = v;
    }
}

// ---------------- pass 2: q GEMM + out = relu(M[b] @ q + bf) ----------------
// smem: xs[CINP][TN] | qs[C2][TN]
__global__ void __launch_bounds__(256, 2)
pass2_kernel(const float* __restrict__ x, float* __restrict__ out) {
    extern __shared__ float smem[];
    float* xs = smem;                 // CINP*TN
    float* qs = smem + CINP * TN;     // C2*TN

    const int tid = threadIdx.x;
    const int tx = tid & 15, ty = tid >> 4;
    const int b = blockIdx.x >> 7, t = blockIdx.x & 127;
    const int n0 = t * TN;
    const float* xb = x + (size_t)b * CIN * NN;

    if (tid < TN) xs[CIN * TN + tid] = 0.f;
    for (int idx = tid; idx < CIN * TN; idx += 256) {
        int k = idx >> 7, n = idx & 127;
        xs[idx] = xb[k * NN + n0 + n];
    }
    __syncthreads();

    gemm_wx<false>(&g_Wq[0][0], xs, g_bq, qs, ty * 8, tx * 8);
    __syncthreads();

    // y[o][n] = sum_c MT[b][c][o] * q[c][n]
    const int o0 = ty * 4, nn0 = tx * 8;
    float acc[4][8];
#pragma unroll
    for (int i = 0; i < 4; ++i)
#pragma unroll
        for (int j = 0; j < 8; ++j) acc[i][j] = 0.f;

#pragma unroll 4
    for (int c = 0; c < C2; ++c) {
        const float4 a  = *reinterpret_cast<const float4*>(&g_MT[b][c][o0]);
        const float4 b0 = *reinterpret_cast<const float4*>(qs + c * TN + nn0);
        const float4 b1 = *reinterpret_cast<const float4*>(qs + c * TN + nn0 + 4);
        const float av[4] = {a.x, a.y, a.z, a.w};
        const float bv[8] = {b0.x, b0.y, b0.z, b0.w, b1.x, b1.y, b1.z, b1.w};
#pragma unroll
        for (int i = 0; i < 4; ++i)
#pragma unroll
            for (int j = 0; j < 8; ++j) acc[i][j] = fmaf(av[i], bv[j], acc[i][j]);
    }

#pragma unroll
    for (int i = 0; i < 4; ++i) {
        const int o = o0 + i;
        const float bias = g_bf[o];
        float4 lo, hi;
        lo.x = fmaxf(acc[i][0] + bias, 0.f);
        lo.y = fmaxf(acc[i][1] + bias, 0.f);
        lo.z = fmaxf(acc[i][2] + bias, 0.f);
        lo.w = fmaxf(acc[i][3] + bias, 0.f);
        hi.x = fmaxf(acc[i][4] + bias, 0.f);
        hi.y = fmaxf(acc[i][5] + bias, 0.f);
        hi.z = fmaxf(acc[i][6] + bias, 0.f);
        hi.w = fmaxf(acc[i][7] + bias, 0.f);
        float* op = out + ((size_t)(b * CO + o)) * NN + n0 + nn0;
        *reinterpret_cast<float4*>(op)     = lo;
        *reinterpret_cast<float4*>(op + 4) = hi;
    }
}

// ---------------- launch ----------------
extern "C" void kernel_launch(void* const* d_in, const int* in_sizes, int n_in,
                              void* d_out, int out_size) {
    const float* x   = (const float*)d_in[0];
    const float* Wq  = (const float*)d_in[1];
    const float* Wk  = (const float*)d_in[2];
    const float* Wv  = (const float*)d_in[3];
    const float* Wf  = (const float*)d_in[4];
    const float* bnq = (const float*)d_in[5];
    const float* bnk = (const float*)d_in[6];
    const float* bnv = (const float*)d_in[7];
    const float* bnf = (const float*)d_in[8];
    float* out = (float*)d_out;

    const int SMEM_P1 = (CINP * TN + 2 * TN * C2) * (int)sizeof(float);   // 165,888 B
    const int SMEM_P2 = (CINP * TN + C2 * TN) * (int)sizeof(float);       // 100,352 B
    const int SMEM_MK = C2 * C2 * (int)sizeof(float);                     //  65,536 B

    cudaFuncSetAttribute(pass1_kernel, cudaFuncAttributeMaxDynamicSharedMemorySize, SMEM_P1);
    cudaFuncSetAttribute(pass2_kernel, cudaFuncAttributeMaxDynamicSharedMemorySize, SMEM_P2);
    cudaFuncSetAttribute(mkernel,      cudaFuncAttributeMaxDynamicSharedMemorySize, SMEM_MK);

    prep_kernel<<<1, 256>>>(Wq, Wk, Wv, Wf, bnq, bnk, bnv, bnf);
    pass1_kernel<<<NPART, 256, SMEM_P1>>>(x);
    mkernel<<<BB, 256, SMEM_MK>>>();
    pass2_kernel<<<BB * (NN / TN), 256, SMEM_P2>>>(x, out);
}